// round 13
// baseline (speedup 1.0000x reference)
#include <cuda_runtime.h>
#include <cuda_fp16.h>
#include <cstdint>

#define NN 100000
#define DD 256
#define NE 3200000
#define SCAN_B 512
#define SCAN_NBLK ((NN + SCAN_B - 1) / SCAN_B)   // 196

// ---------------------------------------------------------------------------
// Device scratch (allocation-free rule: __device__ globals)
// ---------------------------------------------------------------------------
__device__ __half g_support[(size_t)NN * DD];  // x @ W, fp16 (halves gather bytes)
__device__ int    g_count[NN];                 // per-row edge count
__device__ int    g_start[NN + 1];             // CSR row starts (exclusive scan)
__device__ int    g_pos[NN];                   // scatter cursors
__device__ int    g_bsum[SCAN_NBLK];           // scan block totals
__device__ int2   g_edge[NE];                  // edges sorted by row: (col, val bits)

// ---------------------------------------------------------------------------
// tf32 tensor-core GEMM: support[NN,256] = x[NN,256] @ W[256,256]
// 128x128 block tile, 8 warps in 2(M)x4(N), warp tile 64x32, K-chunk 32.
// Epilogue converts to fp16.
// ---------------------------------------------------------------------------
#define AS_STRIDE 36
#define BS_STRIDE 132

__device__ __forceinline__ unsigned f2tf(float f) {
    unsigned r;
    asm("cvt.rna.tf32.f32 %0, %1;" : "=r"(r) : "f"(f));
    return r;
}

__global__ void __launch_bounds__(256, 2) gemm_tc_kernel(const float* __restrict__ A,
                                                         const float* __restrict__ B) {
    __shared__ unsigned As[128 * AS_STRIDE];   // [m][k] tf32 bits
    __shared__ unsigned Bs[32 * BS_STRIDE];    // [k][n] tf32 bits

    const int tid  = threadIdx.x;
    const int warp = tid >> 5;
    const int lane = tid & 31;
    const int g    = lane >> 2;
    const int l    = lane & 3;

    const int wm = warp & 1;
    const int wn = warp >> 1;

    const int row0 = blockIdx.y * 128;
    const int col0 = blockIdx.x * 128;

    float c[4][4][4];
#pragma unroll
    for (int i = 0; i < 4; i++)
#pragma unroll
        for (int j = 0; j < 4; j++)
#pragma unroll
            for (int q = 0; q < 4; q++) c[i][j][q] = 0.0f;

    for (int k0 = 0; k0 < DD; k0 += 32) {
#pragma unroll
        for (int i = 0; i < 4; i++) {
            const int rl = warp * 16 + i * 4 + (lane >> 3);
            int gr = row0 + rl;
            gr = gr < NN ? gr : NN - 1;
            const int f4 = (lane & 7) * 4;
            float4 v = *(const float4*)(A + (size_t)gr * DD + k0 + f4);
            unsigned* d = &As[rl * AS_STRIDE + f4];
            d[0] = f2tf(v.x); d[1] = f2tf(v.y); d[2] = f2tf(v.z); d[3] = f2tf(v.w);
        }
#pragma unroll
        for (int i = 0; i < 4; i++) {
            const int kl = warp * 4 + i;
            float4 v = *(const float4*)(B + (size_t)(k0 + kl) * DD + col0 + lane * 4);
            unsigned* d = &Bs[kl * BS_STRIDE + lane * 4];
            d[0] = f2tf(v.x); d[1] = f2tf(v.y); d[2] = f2tf(v.z); d[3] = f2tf(v.w);
        }
        __syncthreads();

#pragma unroll
        for (int kk = 0; kk < 32; kk += 8) {
            unsigned af[4][4];
#pragma unroll
            for (int i = 0; i < 4; i++) {
                const int mr = wm * 64 + i * 16 + g;
                af[i][0] = As[(mr)     * AS_STRIDE + kk + l];
                af[i][1] = As[(mr + 8) * AS_STRIDE + kk + l];
                af[i][2] = As[(mr)     * AS_STRIDE + kk + l + 4];
                af[i][3] = As[(mr + 8) * AS_STRIDE + kk + l + 4];
            }
            unsigned bf[4][2];
#pragma unroll
            for (int j = 0; j < 4; j++) {
                const int nc = wn * 32 + j * 8 + g;
                bf[j][0] = Bs[(kk + l)     * BS_STRIDE + nc];
                bf[j][1] = Bs[(kk + l + 4) * BS_STRIDE + nc];
            }
#pragma unroll
            for (int i = 0; i < 4; i++)
#pragma unroll
                for (int j = 0; j < 4; j++) {
                    asm volatile(
                        "mma.sync.aligned.m16n8k8.row.col.f32.tf32.tf32.f32 "
                        "{%0,%1,%2,%3}, {%4,%5,%6,%7}, {%8,%9}, {%0,%1,%2,%3};"
                        : "+f"(c[i][j][0]), "+f"(c[i][j][1]),
                          "+f"(c[i][j][2]), "+f"(c[i][j][3])
                        : "r"(af[i][0]), "r"(af[i][1]), "r"(af[i][2]), "r"(af[i][3]),
                          "r"(bf[j][0]), "r"(bf[j][1]));
                }
        }
        __syncthreads();
    }

    // epilogue: fp32 frags -> fp16 pairs. cols (2l, 2l+1) -> one __half2 store.
#pragma unroll
    for (int i = 0; i < 4; i++) {
        const int r_lo = row0 + wm * 64 + i * 16 + g;
        const int r_hi = r_lo + 8;
#pragma unroll
        for (int j = 0; j < 4; j++) {
            const int cc = col0 + wn * 32 + j * 8 + 2 * l;
            if (r_lo < NN)
                *(__half2*)(g_support + (size_t)r_lo * DD + cc) =
                    __floats2half2_rn(c[i][j][0], c[i][j][1]);
            if (r_hi < NN)
                *(__half2*)(g_support + (size_t)r_hi * DD + cc) =
                    __floats2half2_rn(c[i][j][2], c[i][j][3]);
        }
    }
}

// ---------------------------------------------------------------------------
// CSR build: histogram -> exclusive scan (3 kernels) -> scatter
// ---------------------------------------------------------------------------
__global__ void __launch_bounds__(256) zero_count_kernel() {
    int i = blockIdx.x * 256 + threadIdx.x;
    if (i < NN) g_count[i] = 0;
}

__global__ void __launch_bounds__(256) hist_kernel(const int* __restrict__ er, int E) {
    int e = blockIdx.x * 256 + threadIdx.x;
    if (e < E) atomicAdd(&g_count[er[e]], 1);
}

__global__ void __launch_bounds__(SCAN_B) scan1_kernel() {
    __shared__ int sh[SCAN_B];
    int i = blockIdx.x * SCAN_B + threadIdx.x;
    int v = (i < NN) ? g_count[i] : 0;
    sh[threadIdx.x] = v;
    __syncthreads();
#pragma unroll
    for (int off = 1; off < SCAN_B; off <<= 1) {
        int t = (threadIdx.x >= off) ? sh[threadIdx.x - off] : 0;
        __syncthreads();
        sh[threadIdx.x] += t;
        __syncthreads();
    }
    int incl = sh[threadIdx.x];
    if (i < NN) g_start[i] = incl - v;
    if (threadIdx.x == SCAN_B - 1) g_bsum[blockIdx.x] = incl;
}

__global__ void __launch_bounds__(256) scan2_kernel() {
    __shared__ int sh[256];
    int t = threadIdx.x;
    int v = (t < SCAN_NBLK) ? g_bsum[t] : 0;
    sh[t] = v;
    __syncthreads();
#pragma unroll
    for (int off = 1; off < 256; off <<= 1) {
        int p = (t >= off) ? sh[t - off] : 0;
        __syncthreads();
        sh[t] += p;
        __syncthreads();
    }
    if (t < SCAN_NBLK) g_bsum[t] = sh[t] - v;
}

__global__ void __launch_bounds__(256) scan3_kernel(int E) {
    int i = blockIdx.x * 256 + threadIdx.x;
    if (i < NN) {
        int s = g_start[i] + g_bsum[i / SCAN_B];
        g_start[i] = s;
        g_pos[i]   = s;
    } else if (i == NN) {
        g_start[NN] = E;
    }
}

__global__ void __launch_bounds__(256) scatter_kernel(const float* __restrict__ ev,
                                                      const int* __restrict__ er,
                                                      const int* __restrict__ ec,
                                                      int E) {
    int e = blockIdx.x * 256 + threadIdx.x;
    if (e < E) {
        int p = atomicAdd(&g_pos[er[e]], 1);
        g_edge[p] = make_int2(ec[e], __float_as_int(ev[e]));
    }
}

// ---------------------------------------------------------------------------
// Aggregate + ReLU: one warp per row, fp16 support gathers, fp32 accumulate.
// Per edge: ONE float4 load per lane (8 halves) -> 512B/edge L2 traffic.
// ---------------------------------------------------------------------------
__global__ void __launch_bounds__(256) aggregate_kernel(float* __restrict__ out) {
    const int row  = (blockIdx.x * 256 + threadIdx.x) >> 5;
    const int lane = threadIdx.x & 31;
    if (row >= NN) return;

    const int s = g_start[row];
    const int e = g_start[row + 1];

    float a[8];
#pragma unroll
    for (int q = 0; q < 8; q++) a[q] = 0.0f;

    for (int base = s; base < e; base += 32) {
        const int idx = base + lane;
        int2 ed = (idx < e) ? g_edge[idx] : make_int2(0, 0);
        const int n = min(32, e - base);
        for (int j = 0; j < n; j++) {
            const int   cc = __shfl_sync(0xffffffffu, ed.x, j);
            const float vv = __int_as_float(__shfl_sync(0xffffffffu, ed.y, j));
            const float4* sp = (const float4*)(g_support + (size_t)cc * DD);
            float4 raw = __ldg(sp + lane);
            const __half2* h = (const __half2*)&raw;
            float2 f0 = __half22float2(h[0]);
            float2 f1 = __half22float2(h[1]);
            float2 f2 = __half22float2(h[2]);
            float2 f3 = __half22float2(h[3]);
            a[0] += vv * f0.x; a[1] += vv * f0.y;
            a[2] += vv * f1.x; a[3] += vv * f1.y;
            a[4] += vv * f2.x; a[5] += vv * f2.y;
            a[6] += vv * f3.x; a[7] += vv * f3.y;
        }
    }

#pragma unroll
    for (int q = 0; q < 8; q++) a[q] = fmaxf(a[q], 0.0f);

    float4* o = (float4*)(out + (size_t)row * DD + lane * 8);
    o[0] = make_float4(a[0], a[1], a[2], a[3]);
    o[1] = make_float4(a[4], a[5], a[6], a[7]);
}

// ---------------------------------------------------------------------------
// Launch: fork-join two-stream overlap.
//   capture stream : GEMM  (tensor/L1-bound)
//   side stream    : CSR build (L2-atomic/scatter-bound)
//   join, then aggregate (depends on both).
// Streams/events are lazily created ONCE (resource setup, not captured work);
// the captured graph is identical on every capture call.
// ---------------------------------------------------------------------------
extern "C" void kernel_launch(void* const* d_in, const int* in_sizes, int n_in,
                              void* d_out, int out_size) {
    const float* x  = (const float*)d_in[0];
    const float* w  = (const float*)d_in[1];
    const float* ev = (const float*)d_in[2];
    const int*   er = (const int*)d_in[3];
    const int*   ec = (const int*)d_in[4];
    float*       out = (float*)d_out;
    const int E = in_sizes[2];

    const int gE  = (E + 255) / 256;
    const int gN  = (NN + 255) / 256;
    const int gN1 = (NN + 1 + 255) / 256;

    static cudaStream_t s2 = nullptr;
    static cudaEvent_t  ev_fork = nullptr, ev_join = nullptr;
    if (s2 == nullptr) {
        cudaStreamCreateWithFlags(&s2, cudaStreamNonBlocking);
        cudaEventCreateWithFlags(&ev_fork, cudaEventDisableTiming);
        cudaEventCreateWithFlags(&ev_join, cudaEventDisableTiming);
    }

    // Fork: side stream inherits capture dependency from the capture stream.
    cudaEventRecord(ev_fork, 0);
    cudaStreamWaitEvent(s2, ev_fork, 0);

    // Side stream: CSR build chain (independent of GEMM).
    zero_count_kernel<<<gN, 256, 0, s2>>>();
    hist_kernel<<<gE, 256, 0, s2>>>(er, E);
    scan1_kernel<<<SCAN_NBLK, SCAN_B, 0, s2>>>();
    scan2_kernel<<<1, 256, 0, s2>>>();
    scan3_kernel<<<gN1, 256, 0, s2>>>(E);
    scatter_kernel<<<gE, 256, 0, s2>>>(ev, er, ec, E);
    cudaEventRecord(ev_join, s2);

    // Capture stream: GEMM runs concurrently with the CSR build.
    gemm_tc_kernel<<<dim3(DD / 128, (NN + 127) / 128), 256>>>(x, w);

    // Join: aggregate needs both support and the CSR edge list.
    cudaStreamWaitEvent(0, ev_join, 0);
    aggregate_kernel<<<(NN * 32 + 255) / 256, 256>>>(out);
}

// round 14
// speedup vs baseline: 1.3210x; 1.3210x over previous
#include <cuda_runtime.h>
#include <cuda_fp16.h>
#include <cstdint>

#define NN 100000
#define DD 256
#define NE 3200000
#define SCAN_B 512
#define SCAN_NBLK ((NN + SCAN_B - 1) / SCAN_B)   // 196

// ---------------------------------------------------------------------------
// Device scratch (allocation-free rule: __device__ globals)
// ---------------------------------------------------------------------------
__device__ __half g_support[(size_t)NN * DD];  // x @ W, fp16 (halves gather bytes)
__device__ int    g_count[NN];                 // per-row edge count
__device__ int    g_start[NN + 1];             // CSR row starts (exclusive scan)
__device__ int    g_pos[NN];                   // scatter cursors
__device__ int    g_bsum[SCAN_NBLK];           // scan block totals
__device__ int2   g_edge[NE];                  // edges sorted by row: (col, val bits)

// ---------------------------------------------------------------------------
// fp16 tensor-core GEMM: support[NN,256] = x[NN,256] @ W[256,256]
// 128x128 block tile, 8 warps in 2(M)x4(N), warp tile 64x32, K-chunk 32.
// mma.sync.aligned.m16n8k16.row.col.f32.f16.f16.f32  (2 kk-steps per chunk)
// As[m][k] halves, stride 40 (frag reads conflict-free: banks {20g+l}).
// Bs[n][k] halves (W transposed at load), stride 36 (frag reads conflict-free).
// ---------------------------------------------------------------------------
#define AS_STRIDE 40
#define BS_STRIDE 36

__global__ void __launch_bounds__(256, 2) gemm_tc_kernel(const float* __restrict__ A,
                                                         const float* __restrict__ B) {
    __shared__ __half As[128 * AS_STRIDE];   // [m][k]
    __shared__ __half Bs[128 * BS_STRIDE];   // [n][k]  (transposed W tile)

    const int tid  = threadIdx.x;
    const int warp = tid >> 5;
    const int lane = tid & 31;
    const int g    = lane >> 2;   // 0..7
    const int l    = lane & 3;    // 0..3

    const int wm = warp & 1;      // 64-row slab
    const int wn = warp >> 1;     // 32-col slab

    const int row0 = blockIdx.y * 128;
    const int col0 = blockIdx.x * 128;

    float c[4][4][4];
#pragma unroll
    for (int i = 0; i < 4; i++)
#pragma unroll
        for (int j = 0; j < 4; j++)
#pragma unroll
            for (int q = 0; q < 4; q++) c[i][j][q] = 0.0f;

    for (int k0 = 0; k0 < DD; k0 += 32) {
        // --- A tile: 128 rows x 32 k, fp32 -> fp16 ---
#pragma unroll
        for (int i = 0; i < 4; i++) {
            const int rl = warp * 16 + i * 4 + (lane >> 3);   // 0..127
            int gr = row0 + rl;
            gr = gr < NN ? gr : NN - 1;
            const int f4 = (lane & 7) * 4;                    // k offset, mult of 4
            float4 v = *(const float4*)(A + (size_t)gr * DD + k0 + f4);
            __half2* d = (__half2*)(As + rl * AS_STRIDE + f4);
            d[0] = __floats2half2_rn(v.x, v.y);
            d[1] = __floats2half2_rn(v.z, v.w);
        }
        // --- B tile transposed: Bs[n][k] = W[k0+k][col0+n] ---
#pragma unroll
        for (int i = 0; i < 4; i++) {
            const int kl = warp * 4 + i;                      // 0..31
            const int n0 = lane * 4;
            float4 v = *(const float4*)(B + (size_t)(k0 + kl) * DD + col0 + n0);
            Bs[(n0 + 0) * BS_STRIDE + kl] = __float2half_rn(v.x);
            Bs[(n0 + 1) * BS_STRIDE + kl] = __float2half_rn(v.y);
            Bs[(n0 + 2) * BS_STRIDE + kl] = __float2half_rn(v.z);
            Bs[(n0 + 3) * BS_STRIDE + kl] = __float2half_rn(v.w);
        }
        __syncthreads();

#pragma unroll
        for (int kk = 0; kk < 32; kk += 16) {
            unsigned af[4][4];
#pragma unroll
            for (int i = 0; i < 4; i++) {
                const int mr = wm * 64 + i * 16 + g;
                af[i][0] = *(const unsigned*)&As[(mr)     * AS_STRIDE + kk + 2 * l];
                af[i][1] = *(const unsigned*)&As[(mr + 8) * AS_STRIDE + kk + 2 * l];
                af[i][2] = *(const unsigned*)&As[(mr)     * AS_STRIDE + kk + 2 * l + 8];
                af[i][3] = *(const unsigned*)&As[(mr + 8) * AS_STRIDE + kk + 2 * l + 8];
            }
            unsigned bf[4][2];
#pragma unroll
            for (int j = 0; j < 4; j++) {
                const int nc = wn * 32 + j * 8 + g;
                bf[j][0] = *(const unsigned*)&Bs[nc * BS_STRIDE + kk + 2 * l];
                bf[j][1] = *(const unsigned*)&Bs[nc * BS_STRIDE + kk + 2 * l + 8];
            }
#pragma unroll
            for (int i = 0; i < 4; i++)
#pragma unroll
                for (int j = 0; j < 4; j++) {
                    asm volatile(
                        "mma.sync.aligned.m16n8k16.row.col.f32.f16.f16.f32 "
                        "{%0,%1,%2,%3}, {%4,%5,%6,%7}, {%8,%9}, {%0,%1,%2,%3};"
                        : "+f"(c[i][j][0]), "+f"(c[i][j][1]),
                          "+f"(c[i][j][2]), "+f"(c[i][j][3])
                        : "r"(af[i][0]), "r"(af[i][1]), "r"(af[i][2]), "r"(af[i][3]),
                          "r"(bf[j][0]), "r"(bf[j][1]));
                }
        }
        __syncthreads();
    }

    // epilogue: fp32 frags -> fp16 pairs. cols (2l, 2l+1) -> one __half2 store.
#pragma unroll
    for (int i = 0; i < 4; i++) {
        const int r_lo = row0 + wm * 64 + i * 16 + g;
        const int r_hi = r_lo + 8;
#pragma unroll
        for (int j = 0; j < 4; j++) {
            const int cc = col0 + wn * 32 + j * 8 + 2 * l;
            if (r_lo < NN)
                *(__half2*)(g_support + (size_t)r_lo * DD + cc) =
                    __floats2half2_rn(c[i][j][0], c[i][j][1]);
            if (r_hi < NN)
                *(__half2*)(g_support + (size_t)r_hi * DD + cc) =
                    __floats2half2_rn(c[i][j][2], c[i][j][3]);
        }
    }
}

// ---------------------------------------------------------------------------
// CSR build: histogram -> exclusive scan (3 kernels) -> scatter
// ---------------------------------------------------------------------------
__global__ void __launch_bounds__(256) zero_count_kernel() {
    int i = blockIdx.x * 256 + threadIdx.x;
    if (i < NN) g_count[i] = 0;
}

__global__ void __launch_bounds__(256) hist_kernel(const int* __restrict__ er, int E) {
    int e = blockIdx.x * 256 + threadIdx.x;
    if (e < E) atomicAdd(&g_count[er[e]], 1);
}

__global__ void __launch_bounds__(SCAN_B) scan1_kernel() {
    __shared__ int sh[SCAN_B];
    int i = blockIdx.x * SCAN_B + threadIdx.x;
    int v = (i < NN) ? g_count[i] : 0;
    sh[threadIdx.x] = v;
    __syncthreads();
#pragma unroll
    for (int off = 1; off < SCAN_B; off <<= 1) {
        int t = (threadIdx.x >= off) ? sh[threadIdx.x - off] : 0;
        __syncthreads();
        sh[threadIdx.x] += t;
        __syncthreads();
    }
    int incl = sh[threadIdx.x];
    if (i < NN) g_start[i] = incl - v;
    if (threadIdx.x == SCAN_B - 1) g_bsum[blockIdx.x] = incl;
}

__global__ void __launch_bounds__(256) scan2_kernel() {
    __shared__ int sh[256];
    int t = threadIdx.x;
    int v = (t < SCAN_NBLK) ? g_bsum[t] : 0;
    sh[t] = v;
    __syncthreads();
#pragma unroll
    for (int off = 1; off < 256; off <<= 1) {
        int p = (t >= off) ? sh[t - off] : 0;
        __syncthreads();
        sh[t] += p;
        __syncthreads();
    }
    if (t < SCAN_NBLK) g_bsum[t] = sh[t] - v;
}

__global__ void __launch_bounds__(256) scan3_kernel(int E) {
    int i = blockIdx.x * 256 + threadIdx.x;
    if (i < NN) {
        int s = g_start[i] + g_bsum[i / SCAN_B];
        g_start[i] = s;
        g_pos[i]   = s;
    } else if (i == NN) {
        g_start[NN] = E;
    }
}

__global__ void __launch_bounds__(256) scatter_kernel(const float* __restrict__ ev,
                                                      const int* __restrict__ er,
                                                      const int* __restrict__ ec,
                                                      int E) {
    int e = blockIdx.x * 256 + threadIdx.x;
    if (e < E) {
        int p = atomicAdd(&g_pos[er[e]], 1);
        g_edge[p] = make_int2(ec[e], __float_as_int(ev[e]));
    }
}

// ---------------------------------------------------------------------------
// Aggregate + ReLU: one warp per row, fp16 support gathers, fp32 accumulate.
// Per edge: ONE float4 load per lane (8 halves) -> 512B/edge L2 traffic.
// ---------------------------------------------------------------------------
__global__ void __launch_bounds__(256) aggregate_kernel(float* __restrict__ out) {
    const int row  = (blockIdx.x * 256 + threadIdx.x) >> 5;
    const int lane = threadIdx.x & 31;
    if (row >= NN) return;

    const int s = g_start[row];
    const int e = g_start[row + 1];

    float a[8];
#pragma unroll
    for (int q = 0; q < 8; q++) a[q] = 0.0f;

    for (int base = s; base < e; base += 32) {
        const int idx = base + lane;
        int2 ed = (idx < e) ? g_edge[idx] : make_int2(0, 0);
        const int n = min(32, e - base);
        for (int j = 0; j < n; j++) {
            const int   cc = __shfl_sync(0xffffffffu, ed.x, j);
            const float vv = __int_as_float(__shfl_sync(0xffffffffu, ed.y, j));
            const float4* sp = (const float4*)(g_support + (size_t)cc * DD);
            float4 raw = __ldg(sp + lane);
            const __half2* h = (const __half2*)&raw;
            float2 f0 = __half22float2(h[0]);
            float2 f1 = __half22float2(h[1]);
            float2 f2 = __half22float2(h[2]);
            float2 f3 = __half22float2(h[3]);
            a[0] += vv * f0.x; a[1] += vv * f0.y;
            a[2] += vv * f1.x; a[3] += vv * f1.y;
            a[4] += vv * f2.x; a[5] += vv * f2.y;
            a[6] += vv * f3.x; a[7] += vv * f3.y;
        }
    }

#pragma unroll
    for (int q = 0; q < 8; q++) a[q] = fmaxf(a[q], 0.0f);

    float4* o = (float4*)(out + (size_t)row * DD + lane * 8);
    o[0] = make_float4(a[0], a[1], a[2], a[3]);
    o[1] = make_float4(a[4], a[5], a[6], a[7]);
}

// ---------------------------------------------------------------------------
// Launch: SERIAL (R13 two-stream overlap regressed +109us: shared-L2
// contention between GEMM streams and random atomic/scatter traffic).
// ---------------------------------------------------------------------------
extern "C" void kernel_launch(void* const* d_in, const int* in_sizes, int n_in,
                              void* d_out, int out_size) {
    const float* x  = (const float*)d_in[0];
    const float* w  = (const float*)d_in[1];
    const float* ev = (const float*)d_in[2];
    const int*   er = (const int*)d_in[3];
    const int*   ec = (const int*)d_in[4];
    float*       out = (float*)d_out;
    const int E = in_sizes[2];

    const int gE  = (E + 255) / 256;
    const int gN  = (NN + 255) / 256;
    const int gN1 = (NN + 1 + 255) / 256;

    gemm_tc_kernel<<<dim3(DD / 128, (NN + 127) / 128), 256>>>(x, w);
    zero_count_kernel<<<gN, 256>>>();
    hist_kernel<<<gE, 256>>>(er, E);
    scan1_kernel<<<SCAN_NBLK, SCAN_B>>>();
    scan2_kernel<<<1, 256>>>();
    scan3_kernel<<<gN1, 256>>>(E);
    scatter_kernel<<<gE, 256>>>(ev, er, ec, E);
    aggregate_kernel<<<(NN * 32 + 255) / 256, 256>>>(out);
}